// round 4
// baseline (speedup 1.0000x reference)
#include <cuda_runtime.h>
#include <math.h>

// ChamferLoss_31044023616212: one-sided Chamfer distance
//   set1: [2, 8192, 3] f32, set2: [2, 8192, 3] f32 -> scalar f32
//
// FMA-bound formulation with Blackwell packed f32x2 FFMA:
//   per set2 point j precompute a_j = (-2*y0, -2*y1, -2*y2, ||y||^2).
//   m_j = ||y_j||^2 - 2<x, y_j>  via 3 packed FFMA2 per PAIR of j.
//   d(x) = sqrt(max(min_j m_j + ||x||^2, 0))   (same identity as reference)
//
// SMEM holds the full preprocessed set2 batch (128 KB) in pair-transposed
// layout so each broadcast LDS.128 yields two packed f32x2 operands:
//   pair q = (j=2q, j'=2q+1):  { ax,cx, ay,cy, az,cz, aw,cw }

#define BPB      74            // blocks per batch; 74*2 = 148 blocks (1/SM)
#define NBATCH   2
#define NBLOCKS  (BPB * NBATCH)
#define T        128           // 4 warps = 1 per SMSP

__device__ float g_partials[NBLOCKS];

typedef unsigned long long u64;

#if defined(__CUDA_ARCH__) && (__CUDA_ARCH__ >= 1000)
#define HAVE_F32X2 1
#else
#define HAVE_F32X2 0
#endif

__device__ __forceinline__ u64 ffma2(u64 a, u64 b, u64 c) {
#if HAVE_F32X2
    u64 d;
    asm("fma.rn.f32x2 %0, %1, %2, %3;" : "=l"(d) : "l"(a), "l"(b), "l"(c));
    return d;
#else
    float2 af = *(float2*)&a, bf = *(float2*)&b, cf = *(float2*)&c;
    float2 df = make_float2(fmaf(af.x, bf.x, cf.x), fmaf(af.y, bf.y, cf.y));
    return *(u64*)&df;
#endif
}
__device__ __forceinline__ u64 bcast2(float x) {
    u64 r;
    asm("mov.b64 %0, {%1, %1};" : "=l"(r) : "f"(x));
    return r;
}
__device__ __forceinline__ void unpack2(u64 v, float& a, float& b) {
    asm("mov.b64 {%0, %1}, %2;" : "=f"(a), "=f"(b) : "l"(v));
}

extern "C" __global__ void __launch_bounds__(T, 1)
chamfer_main_kernel(const float* __restrict__ set1,
                    const float* __restrict__ set2,
                    int n)
{
    extern __shared__ float s2[];   // n/2 pairs * 8 floats = n*16 bytes

    const int tid = threadIdx.x;
    const int b   = blockIdx.y;

    // ---- cooperative preprocess of set2[b] into pair-transposed SMEM ----
    const float* p2 = set2 + (size_t)b * n * 3;
    for (int j = tid; j < n; j += T) {
        float y0 = p2[3 * j + 0];
        float y1 = p2[3 * j + 1];
        float y2 = p2[3 * j + 2];
        float sq = y0 * y0 + y1 * y1 + y2 * y2;
        int base = (j >> 1) * 8;
        int o    = j & 1;
        s2[base + 0 + o] = -2.0f * y0;
        s2[base + 2 + o] = -2.0f * y1;
        s2[base + 4 + o] = -2.0f * y2;
        s2[base + 6 + o] = sq;
    }
    __syncthreads();

    // ---- each thread owns one set1 point (strided for per-block balance) ----
    const int p = tid * BPB + blockIdx.x;
    const bool active = (p < n);

    float x0 = 0.0f, x1 = 0.0f, x2 = 0.0f;
    if (active) {
        const float* p1 = set1 + ((size_t)b * n + p) * 3;
        x0 = p1[0];
        x1 = p1[1];
        x2 = p1[2];
    }
    const float sq1 = x0 * x0 + x1 * x1 + x2 * x2;

    const u64 X0 = bcast2(x0);
    const u64 X1 = bcast2(x1);
    const u64 X2 = bcast2(x2);

    const ulonglong2* sp = (const ulonglong2*)s2;   // 2 x 16B per pair

    // ---- main loop: 3 FFMA2 + 2 FMNMX + 2 LDS.128 per pair (2 points) ----
    float mn0 = 3.4e38f, mn1 = 3.4e38f, mn2 = 3.4e38f, mn3 = 3.4e38f;
    const int npairs = n >> 1;
    #pragma unroll 8
    for (int q = 0; q < npairs; ++q) {
        ulonglong2 u = sp[2 * q];       // {ax,cx , ay,cy}
        ulonglong2 v = sp[2 * q + 1];   // {az,cz , aw,cw}
        u64 t = ffma2(X0, u.x, ffma2(X1, u.y, ffma2(X2, v.x, v.y)));
        float tl, th;
        unpack2(t, tl, th);
        if (q & 1) {
            mn2 = fminf(mn2, tl);
            mn3 = fminf(mn3, th);
        } else {
            mn0 = fminf(mn0, tl);
            mn1 = fminf(mn1, th);
        }
    }
    float m = fminf(fminf(mn0, mn1), fminf(mn2, mn3));

    float d2   = fmaxf(m + sq1, 0.0f);
    float dist = active ? sqrtf(d2) : 0.0f;

    // ---- deterministic block reduction ----
    #pragma unroll
    for (int o = 16; o > 0; o >>= 1)
        dist += __shfl_xor_sync(0xffffffffu, dist, o);

    __shared__ float wsum[T / 32];
    if ((tid & 31) == 0) wsum[tid >> 5] = dist;
    __syncthreads();

    if (tid == 0) {
        float s = 0.0f;
        #pragma unroll
        for (int w = 0; w < T / 32; ++w) s += wsum[w];
        g_partials[b * BPB + blockIdx.x] = s;
    }
}

__global__ void chamfer_reduce_kernel(float* __restrict__ out, int nparts)
{
    __shared__ float buf[256];
    const int t = threadIdx.x;
    buf[t] = (t < nparts) ? g_partials[t] : 0.0f;
    __syncthreads();
    #pragma unroll
    for (int s = 128; s > 0; s >>= 1) {
        if (t < s) buf[t] += buf[t + s];
        __syncthreads();
    }
    if (t == 0) out[0] = buf[0];
}

extern "C" void kernel_launch(void* const* d_in, const int* in_sizes, int n_in,
                              void* d_out, int out_size)
{
    const float* set1 = (const float*)d_in[0];
    const float* set2 = (const float*)d_in[1];

    // in_sizes[0] = b * n * d = 2 * n * 3
    const int n = in_sizes[0] / (NBATCH * 3);

    const size_t smem = (size_t)n * 4 * sizeof(float);   // 131072 B for n=8192
    cudaFuncSetAttribute(chamfer_main_kernel,
                         cudaFuncAttributeMaxDynamicSharedMemorySize, (int)smem);

    dim3 grid(BPB, NBATCH);
    chamfer_main_kernel<<<grid, T, smem>>>(set1, set2, n);
    chamfer_reduce_kernel<<<1, 256>>>((float*)d_out, NBLOCKS);
}

// round 5
// speedup vs baseline: 1.3330x; 1.3330x over previous
#include <cuda_runtime.h>
#include <math.h>

// ChamferLoss_31044023616212: one-sided Chamfer distance
//   set1: [2, 8192, 3] f32, set2: [2, 8192, 3] f32 -> scalar f32
//
// m_j = ||y_j||^2 - 2<x,y_j> via packed fma.rn.f32x2 (2 set2 points / op),
// d(x) = sqrt(max(min_j m_j + ||x||^2, 0)).  Same identity as reference.
//
// R4 restructure vs 49.2us baseline:
//  * T=512: 8 j-chunks x 64 x-slots. chunk = warp&7 -> SMEM reads are
//    warp-uniform broadcasts (no bank conflicts), 4 warps per SMSP hide
//    LDS/FFMA latency (old version had 1 warp/SMSP -> ~40% issue eff).
//  * 2x set1-point register blocking: 2 LDS.128 amortize over 4 point-pairs.
//  * fused final reduction (last-block pattern) -> no 5us second kernel.

#define BPB      74            // blocks per batch; 74*2 = 148 blocks (1/SM)
#define NBATCH   2
#define NBLOCKS  (BPB * NBATCH)
#define T        512
#define NCHUNK   8             // j-chunks (one per warp group)
#define NSLOT    64            // x-slots per block (2 points each)

__device__ float g_partials[NBLOCKS];
__device__ int   g_count = 0;

typedef unsigned long long u64;

__device__ __forceinline__ u64 ffma2(u64 a, u64 b, u64 c) {
    u64 d;
    asm("fma.rn.f32x2 %0, %1, %2, %3;" : "=l"(d) : "l"(a), "l"(b), "l"(c));
    return d;
}
__device__ __forceinline__ u64 bcast2(float x) {
    u64 r;
    asm("mov.b64 %0, {%1, %1};" : "=l"(r) : "f"(x));
    return r;
}
__device__ __forceinline__ void unpack2(u64 v, float& a, float& b) {
    asm("mov.b64 {%0, %1}, %2;" : "=f"(a), "=f"(b) : "l"(v));
}

extern "C" __global__ void __launch_bounds__(T, 1)
chamfer_main_kernel(const float* __restrict__ set1,
                    const float* __restrict__ set2,
                    float* __restrict__ out,
                    int n)
{
    extern __shared__ float smem[];
    float* s2   = smem;                                   // n*4 floats (pair-transposed)
    float* rbuf = smem + (size_t)n * 4;                   // NSLOT*NCHUNK*2 floats
    float* ssum = rbuf + NSLOT * NCHUNK * 2;              // 2 floats

    const int tid = threadIdx.x;
    const int bx  = blockIdx.x;
    const int b   = blockIdx.y;

    // ---- cooperative preprocess of set2[b] into pair-transposed SMEM ----
    // pair q = (2q, 2q+1): { ax,cx, ay,cy, az,cz, aw,cw },  a=(-2y,|y|^2)
    const float* p2 = set2 + (size_t)b * n * 3;
    for (int j = tid; j < n; j += T) {
        float y0 = p2[3 * j + 0];
        float y1 = p2[3 * j + 1];
        float y2 = p2[3 * j + 2];
        float sq = y0 * y0 + y1 * y1 + y2 * y2;
        int base = (j >> 1) * 8;
        int o    = j & 1;
        s2[base + 0 + o] = -2.0f * y0;
        s2[base + 2 + o] = -2.0f * y1;
        s2[base + 4 + o] = -2.0f * y2;
        s2[base + 6 + o] = sq;
    }
    __syncthreads();

    // ---- thread -> (x-slot, j-chunk); chunk is warp-uniform ----
    const int w     = tid >> 5;
    const int lane  = tid & 31;
    const int chunk = w & 7;               // same for all lanes of a warp
    const int slot  = lane + ((w >> 3) << 5);   // 0..63

    // two set1 points per slot, strided across blocks for balance
    const int pA = slot * BPB + bx;                 // always < n
    const int pB = (slot + NSLOT) * BPB + bx;
    const bool vB = (pB < n);

    const float* base1 = set1 + (size_t)b * n * 3;
    float xa0 = base1[3 * pA + 0], xa1 = base1[3 * pA + 1], xa2 = base1[3 * pA + 2];
    float xb0 = 0.f, xb1 = 0.f, xb2 = 0.f;
    if (vB) {
        xb0 = base1[3 * pB + 0];
        xb1 = base1[3 * pB + 1];
        xb2 = base1[3 * pB + 2];
    }

    const u64 XA0 = bcast2(xa0), XA1 = bcast2(xa1), XA2 = bcast2(xa2);
    const u64 XB0 = bcast2(xb0), XB1 = bcast2(xb1), XB2 = bcast2(xb2);

    const ulonglong2* sp = (const ulonglong2*)s2;  // 2 x 16B per pair
    const int npairs = n >> 1;                     // 4096
    const int QC = npairs / NCHUNK;                // 512 per chunk
    const int q0 = chunk * QC;

    // ---- main loop: 2 LDS.128 + 6 FFMA2 + 4 FMNMX per 4 point-pairs ----
    float mA0 = 3.4e38f, mA1 = 3.4e38f, mB0 = 3.4e38f, mB1 = 3.4e38f;
    #pragma unroll 4
    for (int q = q0; q < q0 + QC; ++q) {
        ulonglong2 u = sp[2 * q];       // {ax,cx , ay,cy}
        ulonglong2 v = sp[2 * q + 1];   // {az,cz , aw,cw}
        u64 tA = ffma2(XA0, u.x, ffma2(XA1, u.y, ffma2(XA2, v.x, v.y)));
        u64 tB = ffma2(XB0, u.x, ffma2(XB1, u.y, ffma2(XB2, v.x, v.y)));
        float al, ah, bl, bh;
        unpack2(tA, al, ah);
        unpack2(tB, bl, bh);
        mA0 = fminf(mA0, al);
        mA1 = fminf(mA1, ah);
        mB0 = fminf(mB0, bl);
        mB1 = fminf(mB1, bh);
    }
    float mA = fminf(mA0, mA1);
    float mB = fminf(mB0, mB1);

    // ---- combine chunks: rbuf[slot][chunk][{A,B}] ----
    rbuf[(slot * NCHUNK + chunk) * 2 + 0] = mA;
    rbuf[(slot * NCHUNK + chunk) * 2 + 1] = mB;
    __syncthreads();

    float dist = 0.0f;
    if (tid < NSLOT) {
        const int s = tid;
        float fA = 3.4e38f, fB = 3.4e38f;
        #pragma unroll
        for (int c = 0; c < NCHUNK; ++c) {
            fA = fminf(fA, rbuf[(s * NCHUNK + c) * 2 + 0]);
            fB = fminf(fB, rbuf[(s * NCHUNK + c) * 2 + 1]);
        }
        const int qA = s * BPB + bx;
        const int qBp = (s + NSLOT) * BPB + bx;
        float a0 = base1[3 * qA + 0], a1 = base1[3 * qA + 1], a2 = base1[3 * qA + 2];
        float sqa = a0 * a0 + a1 * a1 + a2 * a2;
        dist = sqrtf(fmaxf(fA + sqa, 0.0f));
        if (qBp < n) {
            float b0 = base1[3 * qBp + 0], b1 = base1[3 * qBp + 1], b2 = base1[3 * qBp + 2];
            float sqb = b0 * b0 + b1 * b1 + b2 * b2;
            dist += sqrtf(fmaxf(fB + sqb, 0.0f));
        }
        // warp sum over the 2 participating warps (tid 0..63 = warps 0,1 full)
        #pragma unroll
        for (int o = 16; o > 0; o >>= 1)
            dist += __shfl_xor_sync(0xffffffffu, dist, o);
        if (lane == 0) ssum[w] = dist;
    }
    __syncthreads();

    if (tid == 0) {
        float s = ssum[0] + ssum[1];
        g_partials[b * BPB + bx] = s;
        __threadfence();
        int t = atomicAdd(&g_count, 1);
        if (t == NBLOCKS - 1) {
            float tot = 0.0f;
            #pragma unroll 4
            for (int i = 0; i < NBLOCKS; ++i) tot += g_partials[i];
            out[0]  = tot;
            g_count = 0;    // self-reset for graph replay
        }
    }
}

extern "C" void kernel_launch(void* const* d_in, const int* in_sizes, int n_in,
                              void* d_out, int out_size)
{
    const float* set1 = (const float*)d_in[0];
    const float* set2 = (const float*)d_in[1];

    // in_sizes[0] = b * n * d = 2 * n * 3
    const int n = in_sizes[0] / (NBATCH * 3);

    const size_t smem = (size_t)n * 4 * sizeof(float)            // s2
                      + NSLOT * NCHUNK * 2 * sizeof(float)       // rbuf
                      + 16 * sizeof(float);                      // ssum
    cudaFuncSetAttribute(chamfer_main_kernel,
                         cudaFuncAttributeMaxDynamicSharedMemorySize, (int)smem);

    dim3 grid(BPB, NBATCH);
    chamfer_main_kernel<<<grid, T, smem>>>(set1, set2, (float*)d_out, n);
}